// round 15
// baseline (speedup 1.0000x reference)
#include <cuda_runtime.h>
#include <cuda_fp16.h>
#include <cstdint>
#include <cstddef>

#define DECAY 0.9f

#define B_ 2
#define S_ 2048
#define V_ 32000
#define E_ 1024
#define H_ 2048
#define M_ (B_*S_)   // 4096 rows

// Scratch (allocation-free rule: device globals)
__device__ float  g_buf1[(size_t)M_ * H_];    // 32 MB: cur1 (f32)
__device__ float  g_buf2[(size_t)M_ * E_];    // 16 MB: cur2 (f32)
__device__ __half g_s1h [(size_t)M_ * H_];    // 16 MB: spikes1 (fp16)
__device__ __half g_s2h [(size_t)M_ * E_];    //  8 MB: spikes2 (fp16)
__device__ __half g_embH[(size_t)M_ * E_];    //  8 MB: gathered embeddings (fp16)
__device__ __half g_encWt[(size_t)H_ * E_];   //  4 MB: enc_W^T  [H][E]
__device__ __half g_decWt[(size_t)E_ * H_];   //  4 MB: dec_W^T  [E][H]
__device__ __half g_outWt[(size_t)V_ * E_];   // 64 MB: out_W^T  [V][E]
__device__ int    g_ids_is64;

// ---------------------------------------------------------------------------
// helpers
// ---------------------------------------------------------------------------
__device__ __forceinline__ float fast_ex2(float x) {
    float y; asm("ex2.approx.f32 %0, %1;" : "=f"(y) : "f"(x)); return y;
}
__device__ __forceinline__ float fast_rcp(float x) {
    float y; asm("rcp.approx.f32 %0, %1;" : "=f"(y) : "f"(x)); return y;
}
__device__ __forceinline__ void mma16(float* c, const unsigned* a, const unsigned* b) {
    asm volatile(
        "mma.sync.aligned.m16n8k16.row.col.f32.f16.f16.f32 "
        "{%0,%1,%2,%3}, {%4,%5,%6,%7}, {%8,%9}, {%0,%1,%2,%3};\n"
        : "+f"(c[0]), "+f"(c[1]), "+f"(c[2]), "+f"(c[3])
        : "r"(a[0]), "r"(a[1]), "r"(a[2]), "r"(a[3]), "r"(b[0]), "r"(b[1]));
}
__device__ __forceinline__ void ldsm4(unsigned& r0, unsigned& r1, unsigned& r2,
                                      unsigned& r3, uint32_t a) {
    asm volatile("ldmatrix.sync.aligned.m8n8.x4.shared.b16 {%0,%1,%2,%3}, [%4];"
                 : "=r"(r0), "=r"(r1), "=r"(r2), "=r"(r3) : "r"(a));
}
__device__ __forceinline__ uint32_t smem_u32(const void* p) {
    uint32_t a;
    asm("{ .reg .u64 t; cvta.to.shared.u64 t, %1; cvt.u32.u64 %0, t; }" : "=r"(a) : "l"(p));
    return a;
}
__device__ __forceinline__ void cp16(uint32_t s, const void* g) {
    asm volatile("cp.async.cg.shared.global [%0], [%1], 16;" :: "r"(s), "l"(g) : "memory");
}
__device__ __forceinline__ void cp_commit() {
    asm volatile("cp.async.commit_group;" ::: "memory");
}
template<int N>
__device__ __forceinline__ void cp_wait() {
    asm volatile("cp.async.wait_group %0;" :: "n"(N) : "memory");
}

// ---------------------------------------------------------------------------
// dtype sniffer for input_ids (int32 vs int64)
// ---------------------------------------------------------------------------
__global__ void sniff_ids(const int* __restrict__ ids32) {
    if (threadIdx.x == 0 && blockIdx.x == 0) {
        int zeros = 0;
        for (int i = 1; i < 255; i += 2) zeros += (ids32[i] == 0);
        g_ids_is64 = (zeros > 64) ? 1 : 0;
    }
}

// ---------------------------------------------------------------------------
// weight transpose + fp32->fp16:  W[K][N] -> Wt[N][K]
// ---------------------------------------------------------------------------
__global__ void conv_transpose(const float* __restrict__ W, __half* __restrict__ Wt,
                               int K, int N)
{
    __shared__ float ts[64][65];
    const int k0 = blockIdx.y * 64, n0 = blockIdx.x * 64;
    const int t  = threadIdx.x;

    const int lk = t >> 4, ln = (t & 15) * 4;
    #pragma unroll
    for (int i = 0; i < 4; i++) {
        float4 v = *(const float4*)&W[(size_t)(k0 + lk + 16 * i) * N + n0 + ln];
        ts[lk + 16 * i][ln]     = v.x;
        ts[lk + 16 * i][ln + 1] = v.y;
        ts[lk + 16 * i][ln + 2] = v.z;
        ts[lk + 16 * i][ln + 3] = v.w;
    }
    __syncthreads();

    const int sn = t >> 2, sk = (t & 3) * 16;
    uint4 o[2];
    __half2* oh = (__half2*)o;
    #pragma unroll
    for (int j = 0; j < 8; j++)
        oh[j] = __floats2half2_rn(ts[sk + 2*j][sn], ts[sk + 2*j + 1][sn]);
    uint4* dst = (uint4*)&Wt[(size_t)(n0 + sn) * K + k0 + sk];
    dst[0] = o[0];
    dst[1] = o[1];
}

// ---------------------------------------------------------------------------
// embedding gather -> fp16
// ---------------------------------------------------------------------------
__global__ void gather_h(const float* __restrict__ emb, const void* __restrict__ idsv,
                         __half* __restrict__ dst)
{
    const int row = blockIdx.x;
    long long id = g_ids_is64 ? ((const long long*)idsv)[row]
                              : (long long)((const int*)idsv)[row];
    const float4* s = (const float4*)(emb + (size_t)id * E_);
    __half2* d = (__half2*)(dst + (size_t)row * E_);
    const int c = threadIdx.x;            // 256 threads, E/4 = 256 float4
    float4 v = s[c];
    d[2*c]   = __floats2half2_rn(v.x, v.y);
    d[2*c+1] = __floats2half2_rn(v.z, v.w);
}

// ---------------------------------------------------------------------------
// fp16 NT GEMM:  C[M,N](f32) = (A[M,K](h) @ Wt[N,K](h)^T + bias) * rowscale
// Block 128x256x32, 5-stage cp.async, 512 threads / 16 warps (2m x 8n),
// warp tile 64x32, mma.m16n8k16 with ldmatrix.x4.
// SMEM rows pitch 40 halfs (80B) => LDSM conflict-free.
// ---------------------------------------------------------------------------
#define PBM 128
#define PBN 256
#define PBK 32
#define STAGES 5
#define ROW_B 80                              // bytes per smem row (40 halfs)
#define A_BYTES (PBM * ROW_B)                 // 10240
#define B_BYTES (PBN * ROW_B)                 // 20480
#define STG_B (A_BYTES + B_BYTES)             // 30720
#define SMEM_BYTES (STAGES * STG_B)           // 153600

template<bool SCALE>
__global__ void __launch_bounds__(512, 1)
gemm_h(const __half* __restrict__ A, const __half* __restrict__ Wt,
       const float* __restrict__ bias, const float* __restrict__ gains,
       float strength, float* __restrict__ C, int M, int N, int K)
{
    extern __shared__ __align__(16) char sm[];
    const uint32_t sbase = smem_u32(sm);

    const int tid = threadIdx.x;
    const int bm0 = blockIdx.x * PBM;
    const int bn0 = blockIdx.y * PBN;

    // ---- copy mapping: 4 threads per row (16B chunks along K), 512 threads ----
    const int crow = tid >> 2;                // 0..127
    const int cchk = tid & 3;
    const __half* ag = A  + (size_t)(bm0 + crow) * K + cchk * 8;
    const __half* bg = Wt + (size_t)(bn0 + crow) * K + cchk * 8;
    const size_t rowStep = (size_t)128 * K;

    const int niter = K / PBK;

    auto issue = [&](int stage, int k0) {
        const uint32_t sa = sbase + stage * STG_B;
        cp16(sa + crow * ROW_B + cchk * 16, ag + k0);            // A: 128 rows
        const uint32_t sb = sa + A_BYTES;
        #pragma unroll
        for (int j = 0; j < 2; j++)                               // B: 256 rows
            cp16(sb + (crow + 128 * j) * ROW_B + cchk * 16,
                 bg + (size_t)j * rowStep + k0);
    };

    // ---- mma mapping: 16 warps 2m x 8n, warp tile 64x32 ----
    const int lane = tid & 31;
    const int wid  = tid >> 5;
    const int wm   = (wid & 1) * 64;
    const int wn   = (wid >> 1) * 32;
    const int ar   = lane >> 2;                // 0..7
    const int ac   = lane & 3;                 // 0..3

    // ldmatrix lane address offsets (within a stage)
    const int a_row16 = ((lane >> 3) & 1) * 8 + (lane & 7);
    const int a_koff  = (lane >> 4) * 8;              // halfs
    uint32_t aoff[4];
    #pragma unroll
    for (int mi = 0; mi < 4; mi++)
        aoff[mi] = (uint32_t)(wm + mi * 16 + a_row16) * ROW_B + a_koff * 2;
    const int b_rowsel = ((lane >> 4) & 1) * 8 + (lane & 7);
    const int b_koff   = ((lane >> 3) & 1) * 8;       // halfs
    uint32_t boff[2];
    #pragma unroll
    for (int p = 0; p < 2; p++)
        boff[p] = A_BYTES + (uint32_t)(wn + p * 16 + b_rowsel) * ROW_B + b_koff * 2;

    float acc[4][4][4];
    #pragma unroll
    for (int mi = 0; mi < 4; mi++)
        #pragma unroll
        for (int ni = 0; ni < 4; ni++)
            #pragma unroll
            for (int j = 0; j < 4; j++) acc[mi][ni][j] = 0.f;

    #pragma unroll
    for (int s = 0; s < STAGES - 1; s++) {
        if (s < niter) issue(s, s * PBK);
        cp_commit();
    }

    for (int kt = 0; kt < niter; kt++) {
        cp_wait<STAGES - 2>();
        __syncthreads();

        const int nk = kt + STAGES - 1;
        if (nk < niter) issue(nk % STAGES, nk * PBK);
        cp_commit();

        const uint32_t stb = sbase + (uint32_t)(kt % STAGES) * STG_B;

        #pragma unroll
        for (int ks = 0; ks < PBK; ks += 16) {
            const uint32_t kb = ks * 2;        // byte offset along K
            unsigned a[4][4], b[4][2];
            #pragma unroll
            for (int mi = 0; mi < 4; mi++)
                ldsm4(a[mi][0], a[mi][1], a[mi][2], a[mi][3], stb + aoff[mi] + kb);
            #pragma unroll
            for (int p = 0; p < 2; p++)
                ldsm4(b[2*p][0], b[2*p][1], b[2*p+1][0], b[2*p+1][1],
                      stb + boff[p] + kb);
            #pragma unroll
            for (int mi = 0; mi < 4; mi++)
                #pragma unroll
                for (int ni = 0; ni < 4; ni++)
                    mma16(acc[mi][ni], a[mi], b[ni]);
        }
    }

    // ---- epilogue: bias + optional row scale ----
    #pragma unroll
    for (int mi = 0; mi < 4; mi++) {
        const int r0 = bm0 + wm + mi * 16 + ar;
        const int r1 = r0 + 8;
        float s0 = 1.f, s1 = 1.f;
        if (SCALE) {
            s0 = 1.f + strength * (gains[r0] - 1.f);
            s1 = 1.f + strength * (gains[r1] - 1.f);
        }
        #pragma unroll
        for (int ni = 0; ni < 4; ni++) {
            const int col = bn0 + wn + ni * 8 + ac * 2;
            const float b0 = bias[col], b1 = bias[col + 1];
            float2 o0, o1;
            o0.x = (acc[mi][ni][0] + b0) * s0;
            o0.y = (acc[mi][ni][1] + b1) * s0;
            o1.x = (acc[mi][ni][2] + b0) * s1;
            o1.y = (acc[mi][ni][3] + b1) * s1;
            *(float2*)&C[(size_t)r0 * N + col] = o0;
            *(float2*)&C[(size_t)r1 * N + col] = o1;
        }
    }
}

// ---------------------------------------------------------------------------
// GIF scan: cur (f32) -> spikes (fp16); sequential over S per channel.
// 16-wide groups, double-buffered prefetch: loads of group i+1 overlap the
// 16-step serial compute of group i (only 2B/4K channels exist, so ILP is
// the only latency lever).
// ---------------------------------------------------------------------------
__global__ void gif_scan(const float* __restrict__ cur, __half* __restrict__ spk, int D)
{
    const int t = blockIdx.x * blockDim.x + threadIdx.x;
    if (t >= B_ * D) return;
    const int b = t / D, d = t % D;
    const float* p = cur + (size_t)b * S_ * D + d;
    __half* q = spk + (size_t)b * S_ * D + d;

    const float KX = 4.0f * 1.4426950408889634f;  // 4*log2(e)
    float c[2][16];
    #pragma unroll
    for (int i = 0; i < 16; i++) c[0][i] = p[(size_t)i * D];

    float v = 0.f;
    #pragma unroll 1
    for (int s0 = 0; s0 < S_; s0 += 16) {
        const int buf = (s0 >> 4) & 1;
        if (s0 + 16 < S_) {
            #pragma unroll
            for (int i = 0; i < 16; i++)
                c[buf ^ 1][i] = p[(size_t)(s0 + 16 + i) * D];
        }
        #pragma unroll
        for (int i = 0; i < 16; i++) {
            v = fmaf(DECAY, v, c[buf][i]);
            const float e  = fast_ex2(fmaf(-KX, v, KX));   // exp(-4(v-1))
            const float sp = fast_rcp(1.0f + e);
            q[(size_t)(s0 + i) * D] = __float2half_rn(sp);
            v -= sp;
        }
    }
}

// ---------------------------------------------------------------------------
// launch
// ---------------------------------------------------------------------------
extern "C" void kernel_launch(void* const* d_in, const int* in_sizes, int n_in,
                              void* d_out, int out_size)
{
    const void*  ids   = d_in[0];
    const float* gains = (const float*)d_in[1];
    const float* emb   = (const float*)d_in[2];
    const float* encW  = (const float*)d_in[3];
    const float* encb  = (const float*)d_in[4];
    const float* decW  = (const float*)d_in[5];
    const float* decb  = (const float*)d_in[6];
    const float* outW  = (const float*)d_in[7];
    const float* outb  = (const float*)d_in[8];
    float* out = (float*)d_out;

    float  *buf1, *buf2;
    __half *s1h, *s2h, *embH, *encWt, *decWt, *outWt;
    cudaGetSymbolAddress((void**)&buf1,  g_buf1);
    cudaGetSymbolAddress((void**)&buf2,  g_buf2);
    cudaGetSymbolAddress((void**)&s1h,   g_s1h);
    cudaGetSymbolAddress((void**)&s2h,   g_s2h);
    cudaGetSymbolAddress((void**)&embH,  g_embH);
    cudaGetSymbolAddress((void**)&encWt, g_encWt);
    cudaGetSymbolAddress((void**)&decWt, g_decWt);
    cudaGetSymbolAddress((void**)&outWt, g_outWt);

    cudaFuncSetAttribute(gemm_h<true>,  cudaFuncAttributeMaxDynamicSharedMemorySize, SMEM_BYTES);
    cudaFuncSetAttribute(gemm_h<false>, cudaFuncAttributeMaxDynamicSharedMemorySize, SMEM_BYTES);

    sniff_ids<<<1, 32>>>((const int*)ids);

    // fp16 operand prep
    gather_h<<<M_, 256>>>(emb, ids, embH);
    conv_transpose<<<dim3(H_/64, E_/64), 256>>>(encW, encWt, E_, H_);
    conv_transpose<<<dim3(E_/64, H_/64), 256>>>(decW, decWt, H_, E_);
    conv_transpose<<<dim3(V_/64, E_/64), 256>>>(outW, outWt, E_, V_);

    // enc: cur1 = (embH @ encW + encb) * (1+0.3*(g-1))    [4096 x 2048, K=1024]
    gemm_h<true><<<dim3(M_/PBM, H_/PBN), 512, SMEM_BYTES>>>(
        embH, encWt, encb, gains, 0.3f, buf1, M_, H_, E_);
    gif_scan<<<(B_*H_ + 127) / 128, 128>>>(buf1, s1h, H_);

    // dec: cur2 = (spikes1 @ decW + decb) * (1+0.2*(g-1)) [4096 x 1024, K=2048]
    gemm_h<true><<<dim3(M_/PBM, E_/PBN), 512, SMEM_BYTES>>>(
        s1h, decWt, decb, gains, 0.2f, buf2, M_, E_, H_);
    gif_scan<<<(B_*E_ + 127) / 128, 128>>>(buf2, s2h, E_);

    // out: logits = spikes2 @ outW + outb                 [4096 x 32000, K=1024]
    gemm_h<false><<<dim3(M_/PBM, V_/PBN), 512, SMEM_BYTES>>>(
        s2h, outWt, outb, nullptr, 0.f, out, M_, V_, E_);
}

// round 16
// speedup vs baseline: 1.0011x; 1.0011x over previous
#include <cuda_runtime.h>
#include <cuda_fp16.h>
#include <cstdint>
#include <cstddef>

#define DECAY 0.9f

#define B_ 2
#define S_ 2048
#define V_ 32000
#define E_ 1024
#define H_ 2048
#define M_ (B_*S_)   // 4096 rows

// Scratch (allocation-free rule: device globals)
__device__ float  g_buf1[(size_t)M_ * H_];    // 32 MB: cur1 (f32)
__device__ float  g_buf2[(size_t)M_ * E_];    // 16 MB: cur2 (f32)
__device__ __half g_s1h [(size_t)M_ * H_];    // 16 MB: spikes1 (fp16)
__device__ __half g_s2h [(size_t)M_ * E_];    //  8 MB: spikes2 (fp16)
__device__ __half g_embH[(size_t)M_ * E_];    //  8 MB: gathered embeddings (fp16)
__device__ __half g_encWt[(size_t)H_ * E_];   //  4 MB: enc_W^T  [H][E]
__device__ __half g_decWt[(size_t)E_ * H_];   //  4 MB: dec_W^T  [E][H]
__device__ __half g_outWt[(size_t)V_ * E_];   // 64 MB: out_W^T  [V][E]
__device__ int    g_ids_is64;

// ---------------------------------------------------------------------------
// helpers
// ---------------------------------------------------------------------------
__device__ __forceinline__ float fast_ex2(float x) {
    float y; asm("ex2.approx.f32 %0, %1;" : "=f"(y) : "f"(x)); return y;
}
__device__ __forceinline__ float fast_rcp(float x) {
    float y; asm("rcp.approx.f32 %0, %1;" : "=f"(y) : "f"(x)); return y;
}
__device__ __forceinline__ void mma16(float* c, const unsigned* a, const unsigned* b) {
    asm volatile(
        "mma.sync.aligned.m16n8k16.row.col.f32.f16.f16.f32 "
        "{%0,%1,%2,%3}, {%4,%5,%6,%7}, {%8,%9}, {%0,%1,%2,%3};\n"
        : "+f"(c[0]), "+f"(c[1]), "+f"(c[2]), "+f"(c[3])
        : "r"(a[0]), "r"(a[1]), "r"(a[2]), "r"(a[3]), "r"(b[0]), "r"(b[1]));
}
__device__ __forceinline__ void ldsm4(unsigned& r0, unsigned& r1, unsigned& r2,
                                      unsigned& r3, uint32_t a) {
    asm volatile("ldmatrix.sync.aligned.m8n8.x4.shared.b16 {%0,%1,%2,%3}, [%4];"
                 : "=r"(r0), "=r"(r1), "=r"(r2), "=r"(r3) : "r"(a));
}
__device__ __forceinline__ uint32_t smem_u32(const void* p) {
    uint32_t a;
    asm("{ .reg .u64 t; cvta.to.shared.u64 t, %1; cvt.u32.u64 %0, t; }" : "=r"(a) : "l"(p));
    return a;
}
__device__ __forceinline__ void cp16(uint32_t s, const void* g) {
    asm volatile("cp.async.cg.shared.global [%0], [%1], 16;" :: "r"(s), "l"(g) : "memory");
}
__device__ __forceinline__ void cp_commit() {
    asm volatile("cp.async.commit_group;" ::: "memory");
}
template<int N>
__device__ __forceinline__ void cp_wait() {
    asm volatile("cp.async.wait_group %0;" :: "n"(N) : "memory");
}

// ---------------------------------------------------------------------------
// dtype sniffer for input_ids (int32 vs int64)
// ---------------------------------------------------------------------------
__global__ void sniff_ids(const int* __restrict__ ids32) {
    if (threadIdx.x == 0 && blockIdx.x == 0) {
        int zeros = 0;
        for (int i = 1; i < 255; i += 2) zeros += (ids32[i] == 0);
        g_ids_is64 = (zeros > 64) ? 1 : 0;
    }
}

// ---------------------------------------------------------------------------
// weight transpose + fp32->fp16:  W[K][N] -> Wt[N][K]
// ---------------------------------------------------------------------------
__global__ void conv_transpose(const float* __restrict__ W, __half* __restrict__ Wt,
                               int K, int N)
{
    __shared__ float ts[64][65];
    const int k0 = blockIdx.y * 64, n0 = blockIdx.x * 64;
    const int t  = threadIdx.x;

    const int lk = t >> 4, ln = (t & 15) * 4;
    #pragma unroll
    for (int i = 0; i < 4; i++) {
        float4 v = *(const float4*)&W[(size_t)(k0 + lk + 16 * i) * N + n0 + ln];
        ts[lk + 16 * i][ln]     = v.x;
        ts[lk + 16 * i][ln + 1] = v.y;
        ts[lk + 16 * i][ln + 2] = v.z;
        ts[lk + 16 * i][ln + 3] = v.w;
    }
    __syncthreads();

    const int sn = t >> 2, sk = (t & 3) * 16;
    uint4 o[2];
    __half2* oh = (__half2*)o;
    #pragma unroll
    for (int j = 0; j < 8; j++)
        oh[j] = __floats2half2_rn(ts[sk + 2*j][sn], ts[sk + 2*j + 1][sn]);
    uint4* dst = (uint4*)&Wt[(size_t)(n0 + sn) * K + k0 + sk];
    dst[0] = o[0];
    dst[1] = o[1];
}

// ---------------------------------------------------------------------------
// embedding gather -> fp16
// ---------------------------------------------------------------------------
__global__ void gather_h(const float* __restrict__ emb, const void* __restrict__ idsv,
                         __half* __restrict__ dst)
{
    const int row = blockIdx.x;
    long long id = g_ids_is64 ? ((const long long*)idsv)[row]
                              : (long long)((const int*)idsv)[row];
    const float4* s = (const float4*)(emb + (size_t)id * E_);
    __half2* d = (__half2*)(dst + (size_t)row * E_);
    const int c = threadIdx.x;            // 256 threads, E/4 = 256 float4
    float4 v = s[c];
    d[2*c]   = __floats2half2_rn(v.x, v.y);
    d[2*c+1] = __floats2half2_rn(v.z, v.w);
}

// ---------------------------------------------------------------------------
// fp16 NT GEMM:  C[M,N](f32) = (A[M,K](h) @ Wt[N,K](h)^T + bias) * rowscale
// Block 128x256x32, 5-stage cp.async, 512 threads / 16 warps (2m x 8n),
// warp tile 64x32, mma.m16n8k16 with ldmatrix.x4.
// SMEM rows pitch 40 halfs (80B) => LDSM conflict-free.
// ---------------------------------------------------------------------------
#define PBM 128
#define PBN 256
#define PBK 32
#define STAGES 5
#define ROW_B 80                              // bytes per smem row (40 halfs)
#define A_BYTES (PBM * ROW_B)                 // 10240
#define B_BYTES (PBN * ROW_B)                 // 20480
#define STG_B (A_BYTES + B_BYTES)             // 30720
#define SMEM_BYTES (STAGES * STG_B)           // 153600

template<bool SCALE>
__global__ void __launch_bounds__(512, 1)
gemm_h(const __half* __restrict__ A, const __half* __restrict__ Wt,
       const float* __restrict__ bias, const float* __restrict__ gains,
       float strength, float* __restrict__ C, int M, int N, int K)
{
    extern __shared__ __align__(16) char sm[];
    const uint32_t sbase = smem_u32(sm);

    const int tid = threadIdx.x;
    const int bm0 = blockIdx.x * PBM;
    const int bn0 = blockIdx.y * PBN;

    // ---- copy mapping: 4 threads per row (16B chunks along K), 512 threads ----
    const int crow = tid >> 2;                // 0..127
    const int cchk = tid & 3;
    const __half* ag = A  + (size_t)(bm0 + crow) * K + cchk * 8;
    const __half* bg = Wt + (size_t)(bn0 + crow) * K + cchk * 8;
    const size_t rowStep = (size_t)128 * K;

    const int niter = K / PBK;

    auto issue = [&](int stage, int k0) {
        const uint32_t sa = sbase + stage * STG_B;
        cp16(sa + crow * ROW_B + cchk * 16, ag + k0);            // A: 128 rows
        const uint32_t sb = sa + A_BYTES;
        #pragma unroll
        for (int j = 0; j < 2; j++)                               // B: 256 rows
            cp16(sb + (crow + 128 * j) * ROW_B + cchk * 16,
                 bg + (size_t)j * rowStep + k0);
    };

    // ---- mma mapping: 16 warps 2m x 8n, warp tile 64x32 ----
    const int lane = tid & 31;
    const int wid  = tid >> 5;
    const int wm   = (wid & 1) * 64;
    const int wn   = (wid >> 1) * 32;
    const int ar   = lane >> 2;                // 0..7
    const int ac   = lane & 3;                 // 0..3

    // ldmatrix lane address offsets (within a stage)
    const int a_row16 = ((lane >> 3) & 1) * 8 + (lane & 7);
    const int a_koff  = (lane >> 4) * 8;              // halfs
    uint32_t aoff[4];
    #pragma unroll
    for (int mi = 0; mi < 4; mi++)
        aoff[mi] = (uint32_t)(wm + mi * 16 + a_row16) * ROW_B + a_koff * 2;
    const int b_rowsel = ((lane >> 4) & 1) * 8 + (lane & 7);
    const int b_koff   = ((lane >> 3) & 1) * 8;       // halfs
    uint32_t boff[2];
    #pragma unroll
    for (int p = 0; p < 2; p++)
        boff[p] = A_BYTES + (uint32_t)(wn + p * 16 + b_rowsel) * ROW_B + b_koff * 2;

    float acc[4][4][4];
    #pragma unroll
    for (int mi = 0; mi < 4; mi++)
        #pragma unroll
        for (int ni = 0; ni < 4; ni++)
            #pragma unroll
            for (int j = 0; j < 4; j++) acc[mi][ni][j] = 0.f;

    #pragma unroll
    for (int s = 0; s < STAGES - 1; s++) {
        if (s < niter) issue(s, s * PBK);
        cp_commit();
    }

    for (int kt = 0; kt < niter; kt++) {
        cp_wait<STAGES - 2>();
        __syncthreads();

        const int nk = kt + STAGES - 1;
        if (nk < niter) issue(nk % STAGES, nk * PBK);
        cp_commit();

        const uint32_t stb = sbase + (uint32_t)(kt % STAGES) * STG_B;

        #pragma unroll
        for (int ks = 0; ks < PBK; ks += 16) {
            const uint32_t kb = ks * 2;        // byte offset along K
            unsigned a[4][4], b[4][2];
            #pragma unroll
            for (int mi = 0; mi < 4; mi++)
                ldsm4(a[mi][0], a[mi][1], a[mi][2], a[mi][3], stb + aoff[mi] + kb);
            #pragma unroll
            for (int p = 0; p < 2; p++)
                ldsm4(b[2*p][0], b[2*p][1], b[2*p+1][0], b[2*p+1][1],
                      stb + boff[p] + kb);
            #pragma unroll
            for (int mi = 0; mi < 4; mi++)
                #pragma unroll
                for (int ni = 0; ni < 4; ni++)
                    mma16(acc[mi][ni], a[mi], b[ni]);
        }
    }

    // ---- epilogue: bias + optional row scale ----
    #pragma unroll
    for (int mi = 0; mi < 4; mi++) {
        const int r0 = bm0 + wm + mi * 16 + ar;
        const int r1 = r0 + 8;
        float s0 = 1.f, s1 = 1.f;
        if (SCALE) {
            s0 = 1.f + strength * (gains[r0] - 1.f);
            s1 = 1.f + strength * (gains[r1] - 1.f);
        }
        #pragma unroll
        for (int ni = 0; ni < 4; ni++) {
            const int col = bn0 + wn + ni * 8 + ac * 2;
            const float b0 = bias[col], b1 = bias[col + 1];
            float2 o0, o1;
            o0.x = (acc[mi][ni][0] + b0) * s0;
            o0.y = (acc[mi][ni][1] + b1) * s0;
            o1.x = (acc[mi][ni][2] + b0) * s1;
            o1.y = (acc[mi][ni][3] + b1) * s1;
            *(float2*)&C[(size_t)r0 * N + col] = o0;
            *(float2*)&C[(size_t)r1 * N + col] = o1;
        }
    }
}

// ---------------------------------------------------------------------------
// GIF scan: cur (f32) -> spikes (fp16); sequential over S per channel.
// 16-wide groups, double-buffered prefetch: loads of group i+1 overlap the
// 16-step serial compute of group i (only 2B/4K channels exist, so ILP is
// the only latency lever).
// ---------------------------------------------------------------------------
__global__ void gif_scan(const float* __restrict__ cur, __half* __restrict__ spk, int D)
{
    const int t = blockIdx.x * blockDim.x + threadIdx.x;
    if (t >= B_ * D) return;
    const int b = t / D, d = t % D;
    const float* p = cur + (size_t)b * S_ * D + d;
    __half* q = spk + (size_t)b * S_ * D + d;

    const float KX = 4.0f * 1.4426950408889634f;  // 4*log2(e)
    float c[2][16];
    #pragma unroll
    for (int i = 0; i < 16; i++) c[0][i] = p[(size_t)i * D];

    float v = 0.f;
    #pragma unroll 1
    for (int s0 = 0; s0 < S_; s0 += 16) {
        const int buf = (s0 >> 4) & 1;
        if (s0 + 16 < S_) {
            #pragma unroll
            for (int i = 0; i < 16; i++)
                c[buf ^ 1][i] = p[(size_t)(s0 + 16 + i) * D];
        }
        #pragma unroll
        for (int i = 0; i < 16; i++) {
            v = fmaf(DECAY, v, c[buf][i]);
            const float e  = fast_ex2(fmaf(-KX, v, KX));   // exp(-4(v-1))
            const float sp = fast_rcp(1.0f + e);
            q[(size_t)(s0 + i) * D] = __float2half_rn(sp);
            v -= sp;
        }
    }
}

// ---------------------------------------------------------------------------
// launch
// ---------------------------------------------------------------------------
extern "C" void kernel_launch(void* const* d_in, const int* in_sizes, int n_in,
                              void* d_out, int out_size)
{
    const void*  ids   = d_in[0];
    const float* gains = (const float*)d_in[1];
    const float* emb   = (const float*)d_in[2];
    const float* encW  = (const float*)d_in[3];
    const float* encb  = (const float*)d_in[4];
    const float* decW  = (const float*)d_in[5];
    const float* decb  = (const float*)d_in[6];
    const float* outW  = (const float*)d_in[7];
    const float* outb  = (const float*)d_in[8];
    float* out = (float*)d_out;

    float  *buf1, *buf2;
    __half *s1h, *s2h, *embH, *encWt, *decWt, *outWt;
    cudaGetSymbolAddress((void**)&buf1,  g_buf1);
    cudaGetSymbolAddress((void**)&buf2,  g_buf2);
    cudaGetSymbolAddress((void**)&s1h,   g_s1h);
    cudaGetSymbolAddress((void**)&s2h,   g_s2h);
    cudaGetSymbolAddress((void**)&embH,  g_embH);
    cudaGetSymbolAddress((void**)&encWt, g_encWt);
    cudaGetSymbolAddress((void**)&decWt, g_decWt);
    cudaGetSymbolAddress((void**)&outWt, g_outWt);

    cudaFuncSetAttribute(gemm_h<true>,  cudaFuncAttributeMaxDynamicSharedMemorySize, SMEM_BYTES);
    cudaFuncSetAttribute(gemm_h<false>, cudaFuncAttributeMaxDynamicSharedMemorySize, SMEM_BYTES);

    sniff_ids<<<1, 32>>>((const int*)ids);

    // fp16 operand prep
    gather_h<<<M_, 256>>>(emb, ids, embH);
    conv_transpose<<<dim3(H_/64, E_/64), 256>>>(encW, encWt, E_, H_);
    conv_transpose<<<dim3(E_/64, H_/64), 256>>>(decW, decWt, H_, E_);
    conv_transpose<<<dim3(V_/64, E_/64), 256>>>(outW, outWt, E_, V_);

    // enc: cur1 = (embH @ encW + encb) * (1+0.3*(g-1))    [4096 x 2048, K=1024]
    gemm_h<true><<<dim3(M_/PBM, H_/PBN), 512, SMEM_BYTES>>>(
        embH, encWt, encb, gains, 0.3f, buf1, M_, H_, E_);
    gif_scan<<<(B_*H_ + 127) / 128, 128>>>(buf1, s1h, H_);

    // dec: cur2 = (spikes1 @ decW + decb) * (1+0.2*(g-1)) [4096 x 1024, K=2048]
    gemm_h<true><<<dim3(M_/PBM, E_/PBN), 512, SMEM_BYTES>>>(
        s1h, decWt, decb, gains, 0.2f, buf2, M_, E_, H_);
    gif_scan<<<(B_*E_ + 127) / 128, 128>>>(buf2, s2h, E_);

    // out: logits = spikes2 @ outW + outb                 [4096 x 32000, K=1024]
    gemm_h<false><<<dim3(M_/PBM, V_/PBN), 512, SMEM_BYTES>>>(
        s2h, outWt, outb, nullptr, 0.f, out, M_, V_, E_);
}

// round 17
// speedup vs baseline: 1.0019x; 1.0007x over previous
#include <cuda_runtime.h>
#include <cuda_fp16.h>
#include <cstdint>
#include <cstddef>

#define DECAY 0.9f

#define B_ 2
#define S_ 2048
#define V_ 32000
#define E_ 1024
#define H_ 2048
#define M_ (B_*S_)   // 4096 rows

// Scratch (allocation-free rule: device globals)
__device__ float  g_buf1[(size_t)M_ * H_];    // 32 MB: cur1 (f32)
__device__ float  g_buf2[(size_t)M_ * E_];    // 16 MB: cur2 (f32)
__device__ __half g_s1h [(size_t)M_ * H_];    // 16 MB: spikes1 (fp16)
__device__ __half g_s2h [(size_t)M_ * E_];    //  8 MB: spikes2 (fp16)
__device__ __half g_embH[(size_t)M_ * E_];    //  8 MB: gathered embeddings (fp16)
__device__ __half g_encWt[(size_t)H_ * E_];   //  4 MB: enc_W^T  [H][E]
__device__ __half g_decWt[(size_t)E_ * H_];   //  4 MB: dec_W^T  [E][H]
__device__ __half g_outWt[(size_t)V_ * E_];   // 64 MB: out_W^T  [V][E]
__device__ int    g_ids_is64;

// ---------------------------------------------------------------------------
// helpers
// ---------------------------------------------------------------------------
__device__ __forceinline__ float fast_ex2(float x) {
    float y; asm("ex2.approx.f32 %0, %1;" : "=f"(y) : "f"(x)); return y;
}
__device__ __forceinline__ float fast_rcp(float x) {
    float y; asm("rcp.approx.f32 %0, %1;" : "=f"(y) : "f"(x)); return y;
}
__device__ __forceinline__ void mma16(float* c, const unsigned* a, const unsigned* b) {
    asm volatile(
        "mma.sync.aligned.m16n8k16.row.col.f32.f16.f16.f32 "
        "{%0,%1,%2,%3}, {%4,%5,%6,%7}, {%8,%9}, {%0,%1,%2,%3};\n"
        : "+f"(c[0]), "+f"(c[1]), "+f"(c[2]), "+f"(c[3])
        : "r"(a[0]), "r"(a[1]), "r"(a[2]), "r"(a[3]), "r"(b[0]), "r"(b[1]));
}
__device__ __forceinline__ void ldsm4(unsigned& r0, unsigned& r1, unsigned& r2,
                                      unsigned& r3, uint32_t a) {
    asm volatile("ldmatrix.sync.aligned.m8n8.x4.shared.b16 {%0,%1,%2,%3}, [%4];"
                 : "=r"(r0), "=r"(r1), "=r"(r2), "=r"(r3) : "r"(a));
}
__device__ __forceinline__ uint32_t smem_u32(const void* p) {
    uint32_t a;
    asm("{ .reg .u64 t; cvta.to.shared.u64 t, %1; cvt.u32.u64 %0, t; }" : "=r"(a) : "l"(p));
    return a;
}
__device__ __forceinline__ void cp16(uint32_t s, const void* g) {
    asm volatile("cp.async.cg.shared.global [%0], [%1], 16;" :: "r"(s), "l"(g) : "memory");
}
__device__ __forceinline__ void cp_commit() {
    asm volatile("cp.async.commit_group;" ::: "memory");
}
template<int N>
__device__ __forceinline__ void cp_wait() {
    asm volatile("cp.async.wait_group %0;" :: "n"(N) : "memory");
}

// ---------------------------------------------------------------------------
// dtype sniffer for input_ids (int32 vs int64)
// ---------------------------------------------------------------------------
__global__ void sniff_ids(const int* __restrict__ ids32) {
    if (threadIdx.x == 0 && blockIdx.x == 0) {
        int zeros = 0;
        for (int i = 1; i < 255; i += 2) zeros += (ids32[i] == 0);
        g_ids_is64 = (zeros > 64) ? 1 : 0;
    }
}

// ---------------------------------------------------------------------------
// weight transpose + fp32->fp16:  W[K][N] -> Wt[N][K]
// ---------------------------------------------------------------------------
__global__ void conv_transpose(const float* __restrict__ W, __half* __restrict__ Wt,
                               int K, int N)
{
    __shared__ float ts[64][65];
    const int k0 = blockIdx.y * 64, n0 = blockIdx.x * 64;
    const int t  = threadIdx.x;

    const int lk = t >> 4, ln = (t & 15) * 4;
    #pragma unroll
    for (int i = 0; i < 4; i++) {
        float4 v = *(const float4*)&W[(size_t)(k0 + lk + 16 * i) * N + n0 + ln];
        ts[lk + 16 * i][ln]     = v.x;
        ts[lk + 16 * i][ln + 1] = v.y;
        ts[lk + 16 * i][ln + 2] = v.z;
        ts[lk + 16 * i][ln + 3] = v.w;
    }
    __syncthreads();

    const int sn = t >> 2, sk = (t & 3) * 16;
    uint4 o[2];
    __half2* oh = (__half2*)o;
    #pragma unroll
    for (int j = 0; j < 8; j++)
        oh[j] = __floats2half2_rn(ts[sk + 2*j][sn], ts[sk + 2*j + 1][sn]);
    uint4* dst = (uint4*)&Wt[(size_t)(n0 + sn) * K + k0 + sk];
    dst[0] = o[0];
    dst[1] = o[1];
}

// ---------------------------------------------------------------------------
// embedding gather -> fp16
// ---------------------------------------------------------------------------
__global__ void gather_h(const float* __restrict__ emb, const void* __restrict__ idsv,
                         __half* __restrict__ dst)
{
    const int row = blockIdx.x;
    long long id = g_ids_is64 ? ((const long long*)idsv)[row]
                              : (long long)((const int*)idsv)[row];
    const float4* s = (const float4*)(emb + (size_t)id * E_);
    __half2* d = (__half2*)(dst + (size_t)row * E_);
    const int c = threadIdx.x;            // 256 threads, E/4 = 256 float4
    float4 v = s[c];
    d[2*c]   = __floats2half2_rn(v.x, v.y);
    d[2*c+1] = __floats2half2_rn(v.z, v.w);
}

// ---------------------------------------------------------------------------
// fp16 NT GEMM:  C[M,N](f32) = (A[M,K](h) @ Wt[N,K](h)^T + bias) * rowscale
// Block 128x256x32, 5-stage cp.async, 512 threads / 16 warps (2m x 8n),
// warp tile 64x32, mma.m16n8k16 with ldmatrix.x4.
// SMEM rows pitch 40 halfs (80B) => LDSM conflict-free.
// ---------------------------------------------------------------------------
#define PBM 128
#define PBN 256
#define PBK 32
#define STAGES 5
#define ROW_B 80                              // bytes per smem row (40 halfs)
#define A_BYTES (PBM * ROW_B)                 // 10240
#define B_BYTES (PBN * ROW_B)                 // 20480
#define STG_B (A_BYTES + B_BYTES)             // 30720
#define SMEM_BYTES (STAGES * STG_B)           // 153600

template<bool SCALE>
__global__ void __launch_bounds__(512, 1)
gemm_h(const __half* __restrict__ A, const __half* __restrict__ Wt,
       const float* __restrict__ bias, const float* __restrict__ gains,
       float strength, float* __restrict__ C, int M, int N, int K)
{
    extern __shared__ __align__(16) char sm[];
    const uint32_t sbase = smem_u32(sm);

    const int tid = threadIdx.x;
    const int bm0 = blockIdx.x * PBM;
    const int bn0 = blockIdx.y * PBN;

    // ---- copy mapping: 4 threads per row (16B chunks along K), 512 threads ----
    const int crow = tid >> 2;                // 0..127
    const int cchk = tid & 3;
    const __half* ag = A  + (size_t)(bm0 + crow) * K + cchk * 8;
    const __half* bg = Wt + (size_t)(bn0 + crow) * K + cchk * 8;
    const size_t rowStep = (size_t)128 * K;

    const int niter = K / PBK;

    auto issue = [&](int stage, int k0) {
        const uint32_t sa = sbase + stage * STG_B;
        cp16(sa + crow * ROW_B + cchk * 16, ag + k0);            // A: 128 rows
        const uint32_t sb = sa + A_BYTES;
        #pragma unroll
        for (int j = 0; j < 2; j++)                               // B: 256 rows
            cp16(sb + (crow + 128 * j) * ROW_B + cchk * 16,
                 bg + (size_t)j * rowStep + k0);
    };

    // ---- mma mapping: 16 warps 2m x 8n, warp tile 64x32 ----
    const int lane = tid & 31;
    const int wid  = tid >> 5;
    const int wm   = (wid & 1) * 64;
    const int wn   = (wid >> 1) * 32;
    const int ar   = lane >> 2;                // 0..7
    const int ac   = lane & 3;                 // 0..3

    // ldmatrix lane address offsets (within a stage)
    const int a_row16 = ((lane >> 3) & 1) * 8 + (lane & 7);
    const int a_koff  = (lane >> 4) * 8;              // halfs
    uint32_t aoff[4];
    #pragma unroll
    for (int mi = 0; mi < 4; mi++)
        aoff[mi] = (uint32_t)(wm + mi * 16 + a_row16) * ROW_B + a_koff * 2;
    const int b_rowsel = ((lane >> 4) & 1) * 8 + (lane & 7);
    const int b_koff   = ((lane >> 3) & 1) * 8;       // halfs
    uint32_t boff[2];
    #pragma unroll
    for (int p = 0; p < 2; p++)
        boff[p] = A_BYTES + (uint32_t)(wn + p * 16 + b_rowsel) * ROW_B + b_koff * 2;

    float acc[4][4][4];
    #pragma unroll
    for (int mi = 0; mi < 4; mi++)
        #pragma unroll
        for (int ni = 0; ni < 4; ni++)
            #pragma unroll
            for (int j = 0; j < 4; j++) acc[mi][ni][j] = 0.f;

    #pragma unroll
    for (int s = 0; s < STAGES - 1; s++) {
        if (s < niter) issue(s, s * PBK);
        cp_commit();
    }

    for (int kt = 0; kt < niter; kt++) {
        cp_wait<STAGES - 2>();
        __syncthreads();

        const int nk = kt + STAGES - 1;
        if (nk < niter) issue(nk % STAGES, nk * PBK);
        cp_commit();

        const uint32_t stb = sbase + (uint32_t)(kt % STAGES) * STG_B;

        #pragma unroll
        for (int ks = 0; ks < PBK; ks += 16) {
            const uint32_t kb = ks * 2;        // byte offset along K
            unsigned a[4][4], b[4][2];
            #pragma unroll
            for (int mi = 0; mi < 4; mi++)
                ldsm4(a[mi][0], a[mi][1], a[mi][2], a[mi][3], stb + aoff[mi] + kb);
            #pragma unroll
            for (int p = 0; p < 2; p++)
                ldsm4(b[2*p][0], b[2*p][1], b[2*p+1][0], b[2*p+1][1],
                      stb + boff[p] + kb);
            #pragma unroll
            for (int mi = 0; mi < 4; mi++)
                #pragma unroll
                for (int ni = 0; ni < 4; ni++)
                    mma16(acc[mi][ni], a[mi], b[ni]);
        }
    }

    // ---- epilogue: bias + optional row scale ----
    #pragma unroll
    for (int mi = 0; mi < 4; mi++) {
        const int r0 = bm0 + wm + mi * 16 + ar;
        const int r1 = r0 + 8;
        float s0 = 1.f, s1 = 1.f;
        if (SCALE) {
            s0 = 1.f + strength * (gains[r0] - 1.f);
            s1 = 1.f + strength * (gains[r1] - 1.f);
        }
        #pragma unroll
        for (int ni = 0; ni < 4; ni++) {
            const int col = bn0 + wn + ni * 8 + ac * 2;
            const float b0 = bias[col], b1 = bias[col + 1];
            float2 o0, o1;
            o0.x = (acc[mi][ni][0] + b0) * s0;
            o0.y = (acc[mi][ni][1] + b1) * s0;
            o1.x = (acc[mi][ni][2] + b0) * s1;
            o1.y = (acc[mi][ni][3] + b1) * s1;
            *(float2*)&C[(size_t)r0 * N + col] = o0;
            *(float2*)&C[(size_t)r1 * N + col] = o1;
        }
    }
}

// ---------------------------------------------------------------------------
// GIF scan: cur (f32) -> spikes (fp16); sequential over S per channel.
// 16-wide groups, double-buffered prefetch: loads of group i+1 overlap the
// 16-step serial compute of group i (only 2B/4K channels exist, so ILP is
// the only latency lever).
// ---------------------------------------------------------------------------
__global__ void gif_scan(const float* __restrict__ cur, __half* __restrict__ spk, int D)
{
    const int t = blockIdx.x * blockDim.x + threadIdx.x;
    if (t >= B_ * D) return;
    const int b = t / D, d = t % D;
    const float* p = cur + (size_t)b * S_ * D + d;
    __half* q = spk + (size_t)b * S_ * D + d;

    const float KX = 4.0f * 1.4426950408889634f;  // 4*log2(e)
    float c[2][16];
    #pragma unroll
    for (int i = 0; i < 16; i++) c[0][i] = p[(size_t)i * D];

    float v = 0.f;
    #pragma unroll 1
    for (int s0 = 0; s0 < S_; s0 += 16) {
        const int buf = (s0 >> 4) & 1;
        if (s0 + 16 < S_) {
            #pragma unroll
            for (int i = 0; i < 16; i++)
                c[buf ^ 1][i] = p[(size_t)(s0 + 16 + i) * D];
        }
        #pragma unroll
        for (int i = 0; i < 16; i++) {
            v = fmaf(DECAY, v, c[buf][i]);
            const float e  = fast_ex2(fmaf(-KX, v, KX));   // exp(-4(v-1))
            const float sp = fast_rcp(1.0f + e);
            q[(size_t)(s0 + i) * D] = __float2half_rn(sp);
            v -= sp;
        }
    }
}

// ---------------------------------------------------------------------------
// launch
// ---------------------------------------------------------------------------
extern "C" void kernel_launch(void* const* d_in, const int* in_sizes, int n_in,
                              void* d_out, int out_size)
{
    const void*  ids   = d_in[0];
    const float* gains = (const float*)d_in[1];
    const float* emb   = (const float*)d_in[2];
    const float* encW  = (const float*)d_in[3];
    const float* encb  = (const float*)d_in[4];
    const float* decW  = (const float*)d_in[5];
    const float* decb  = (const float*)d_in[6];
    const float* outW  = (const float*)d_in[7];
    const float* outb  = (const float*)d_in[8];
    float* out = (float*)d_out;

    float  *buf1, *buf2;
    __half *s1h, *s2h, *embH, *encWt, *decWt, *outWt;
    cudaGetSymbolAddress((void**)&buf1,  g_buf1);
    cudaGetSymbolAddress((void**)&buf2,  g_buf2);
    cudaGetSymbolAddress((void**)&s1h,   g_s1h);
    cudaGetSymbolAddress((void**)&s2h,   g_s2h);
    cudaGetSymbolAddress((void**)&embH,  g_embH);
    cudaGetSymbolAddress((void**)&encWt, g_encWt);
    cudaGetSymbolAddress((void**)&decWt, g_decWt);
    cudaGetSymbolAddress((void**)&outWt, g_outWt);

    cudaFuncSetAttribute(gemm_h<true>,  cudaFuncAttributeMaxDynamicSharedMemorySize, SMEM_BYTES);
    cudaFuncSetAttribute(gemm_h<false>, cudaFuncAttributeMaxDynamicSharedMemorySize, SMEM_BYTES);

    sniff_ids<<<1, 32>>>((const int*)ids);

    // fp16 operand prep
    gather_h<<<M_, 256>>>(emb, ids, embH);
    conv_transpose<<<dim3(H_/64, E_/64), 256>>>(encW, encWt, E_, H_);
    conv_transpose<<<dim3(E_/64, H_/64), 256>>>(decW, decWt, H_, E_);
    conv_transpose<<<dim3(V_/64, E_/64), 256>>>(outW, outWt, E_, V_);

    // enc: cur1 = (embH @ encW + encb) * (1+0.3*(g-1))    [4096 x 2048, K=1024]
    gemm_h<true><<<dim3(M_/PBM, H_/PBN), 512, SMEM_BYTES>>>(
        embH, encWt, encb, gains, 0.3f, buf1, M_, H_, E_);
    gif_scan<<<(B_*H_ + 127) / 128, 128>>>(buf1, s1h, H_);

    // dec: cur2 = (spikes1 @ decW + decb) * (1+0.2*(g-1)) [4096 x 1024, K=2048]
    gemm_h<true><<<dim3(M_/PBM, E_/PBN), 512, SMEM_BYTES>>>(
        s1h, decWt, decb, gains, 0.2f, buf2, M_, E_, H_);
    gif_scan<<<(B_*E_ + 127) / 128, 128>>>(buf2, s2h, E_);

    // out: logits = spikes2 @ outW + outb                 [4096 x 32000, K=1024]
    gemm_h<false><<<dim3(M_/PBM, V_/PBN), 512, SMEM_BYTES>>>(
        s2h, outWt, outb, nullptr, 0.f, out, M_, V_, E_);
}